// round 16
// baseline (speedup 1.0000x reference)
#include <cuda_runtime.h>
#include <stdint.h>

#define N 96
#define D 64
#define C 21
#define MARGIN_F 0.3f
#define ONE_F_BITS 0x3F800000u

#define TJ 8
#define TK 8
#define NZPAIR 66               // #(jt,kt) with jt>kt
#define NWPAIR 78               // #(jt,kt) with jt<=kt

#define NBLK_PREP  N                      // 96
#define NBLK_ZERO  (NZPAIR * N)           // 6336
#define NBLK_WORK  (NWPAIR * N)           // 7488
#define ZERO_BASE  NBLK_PREP              // 96
#define WORK_BASE  (NBLK_PREP + NBLK_ZERO) // 6432
#define NBLK_TOTAL (WORK_BASE + NBLK_WORK) // 13920

// Scratch (no allocations allowed in kernel_launch)
__device__ unsigned char  g_sames[N * N];
// B[i,p,n] float-encoded (0x0 / 0x3F800000), 24 uint4 per (i,p). 3.4 MB, L2-resident.
__device__ uint4          g_B4[N * N * 24];
// prep-done counter; reset to 0 each call by a D2D memcpy node (g_zero -> g_flag)
__device__ int            g_flag;
__device__ const int      g_zero = 0;

// tile-pair lookup tables (literal -> zero decode cost)
__constant__ uint8_t ZJT[NZPAIR] = {
    1,
    2,2,
    3,3,3,
    4,4,4,4,
    5,5,5,5,5,
    6,6,6,6,6,6,
    7,7,7,7,7,7,7,
    8,8,8,8,8,8,8,8,
    9,9,9,9,9,9,9,9,9,
    10,10,10,10,10,10,10,10,10,10,
    11,11,11,11,11,11,11,11,11,11,11 };
__constant__ uint8_t ZKT[NZPAIR] = {
    0,
    0,1,
    0,1,2,
    0,1,2,3,
    0,1,2,3,4,
    0,1,2,3,4,5,
    0,1,2,3,4,5,6,
    0,1,2,3,4,5,6,7,
    0,1,2,3,4,5,6,7,8,
    0,1,2,3,4,5,6,7,8,9,
    0,1,2,3,4,5,6,7,8,9,10 };
__constant__ uint8_t WJT[NWPAIR] = {
    0,0,0,0,0,0,0,0,0,0,0,0,
    1,1,1,1,1,1,1,1,1,1,1,
    2,2,2,2,2,2,2,2,2,2,
    3,3,3,3,3,3,3,3,3,
    4,4,4,4,4,4,4,4,
    5,5,5,5,5,5,5,
    6,6,6,6,6,6,
    7,7,7,7,7,
    8,8,8,8,
    9,9,9,
    10,10,
    11 };
__constant__ uint8_t WKT[NWPAIR] = {
    0,1,2,3,4,5,6,7,8,9,10,11,
    1,2,3,4,5,6,7,8,9,10,11,
    2,3,4,5,6,7,8,9,10,11,
    3,4,5,6,7,8,9,10,11,
    4,5,6,7,8,9,10,11,
    5,6,7,8,9,10,11,
    6,7,8,9,10,11,
    7,8,9,10,11,
    8,9,10,11,
    9,10,11,
    10,11,
    11 };

// ---------------------------------------------------------------------------
// ONE kernel, roles by bid range (R12's proven configuration), plus a
// zero-overhead prep->work handshake:
//   prep:  threadfence + atomicAdd(&g_flag, 1)            (96 arrivals)
//   work:  every thread: one ld.acquire.gpu poll of g_flag (no barrier,
//          no retire atomic; preps finish long before work blocks launch,
//          so the poll is a single L2 broadcast read in steady state)
// g_flag is reset by a D2D memcpy node before the kernel in every call.
// ---------------------------------------------------------------------------
__global__ __launch_bounds__(256, 6)
void miner_kernel(const float* __restrict__ logits,
                  const float* __restrict__ labels,
                  const float* __restrict__ feat2,
                  uint4* __restrict__ out) {
    const int bid = blockIdx.x;
    const int t   = threadIdx.x;

    // ======================= role 1: prep (bids 0..95) =====================
    if (bid < NBLK_PREP) {
        const int i = bid;
        const int j = t;

        __shared__ float         xs[D];
        __shared__ float         li[C];
        __shared__ float         inv_nx;
        __shared__ float         mrow[N];
        __shared__ unsigned char drow[N];

        if (j < D) xs[j] = logits[i * D + j];
        if (j < C) li[j] = labels[i * C + j];
        __syncthreads();

        if (j == 0) {
            float s = 0.f;
            #pragma unroll
            for (int c = 0; c < D; c++) s += xs[c] * xs[c];
            inv_nx = 1.0f / fmaxf(sqrtf(s), 1e-12f);
        }
        __syncthreads();

        if (j < N) {
            float dot = 0.f, nyy = 0.f;
            #pragma unroll
            for (int c = 0; c < D; c++) {
                float y = feat2[j * D + c];
                dot += xs[c] * y;
                nyy += y * y;
            }
            const float inv_ny = 1.0f / fmaxf(sqrtf(nyy), 1e-12f);
            mrow[j] = -(dot * inv_nx * inv_ny);

            float ld = 0.f;
            #pragma unroll
            for (int c = 0; c < C; c++) ld += li[c] * labels[j * C + c];
            const bool share = (ld > 0.0f);
            g_sames[i * N + j] = (share && (i != j)) ? 1 : 0;
            drow[j] = share ? 0 : 1;         // diagonal NOT filled (matches ref)
        }
        __syncthreads();

        if (j < N) {
            const float mp = mrow[j];
            uint4* dst = &g_B4[(i * N + j) * 24];
            #pragma unroll
            for (int v = 0; v < 24; v++) {
                uint4 w;
                w.x = (drow[4*v+0] && (mrow[4*v+0] - mp <= MARGIN_F)) ? ONE_F_BITS : 0u;
                w.y = (drow[4*v+1] && (mrow[4*v+1] - mp <= MARGIN_F)) ? ONE_F_BITS : 0u;
                w.z = (drow[4*v+2] && (mrow[4*v+2] - mp <= MARGIN_F)) ? ONE_F_BITS : 0u;
                w.w = (drow[4*v+3] && (mrow[4*v+3] - mp <= MARGIN_F)) ? ONE_F_BITS : 0u;
                dst[v] = w;
            }
        }

        // signal: this i-slab of g_B4 / g_sames is globally visible
        __syncthreads();
        if (t == 0) {
            __threadfence();
            atomicAdd(&g_flag, 1);
        }
        return;
    }

    // ================= role 2: zero-fill (bids 96..6431) ===================
    if (bid < WORK_BASE) {
        const int z  = bid - ZERO_BASE;
        const int i  = z / NZPAIR;
        const int p  = z - i * NZPAIR;
        const int j0 = (int)ZJT[p] * TJ;
        const int k0 = (int)ZKT[p] * TK;

        uint4* __restrict__ obase = out + ((size_t)(i * N + j0) * N + k0) * 24;
        const uint4 zv = make_uint4(0u, 0u, 0u, 0u);
        #pragma unroll
        for (int it = 0; it < 6; it++) {
            const int l  = it * 256 + t;            // 0..1535
            const int jj = l / (TK * 24);
            const int r  = l - jj * (TK * 24);
            obase[(size_t)jj * (N * 24) + r] = zv;
        }
        return;
    }

    // ================= role 3: work-fill (bids 6432..13919) ================
    {
        // per-thread acquire poll; no barrier, no blocking atomic.
        // In steady state g_flag==96 long before any work block launches,
        // so this is exactly one warp-broadcast L2 read per thread.
        int f;
        do {
            asm volatile("ld.acquire.gpu.u32 %0, [%1];"
                         : "=r"(f) : "l"(&g_flag) : "memory");
        } while (f < NBLK_PREP);

        const int w  = bid - WORK_BASE;
        const int i  = w / NWPAIR;
        const int q  = w - i * NWPAIR;
        const int jt = (int)WJT[q];
        const int kt = (int)WKT[q];
        const int j0 = jt * TJ;
        const int k0 = kt * TK;

        uint4* __restrict__ obase = out + ((size_t)(i * N + j0) * N + k0) * 24;

        __shared__ uint4         sBj[TJ][24];
        __shared__ uint4         sBk[TK][24];
        __shared__ unsigned char ssj[TJ];
        __shared__ unsigned char ssk[TK];

        // load 384 uint4 (rows 0-7 -> sBj, 8-15 -> sBk)
        {
            int l = t;
            {
                const int row = l / 24, v = l % 24;
                const int src_p = (row < TJ) ? (j0 + row) : (k0 + row - TJ);
                uint4 val = g_B4[(i * N + src_p) * 24 + v];
                if (row < TJ) sBj[row][v] = val; else sBk[row - TJ][v] = val;
            }
            l = t + 256;
            if (l < 384) {
                const int row = l / 24, v = l % 24;
                const int src_p = (row < TJ) ? (j0 + row) : (k0 + row - TJ);
                uint4 val = g_B4[(i * N + src_p) * 24 + v];
                if (row < TJ) sBj[row][v] = val; else sBk[row - TJ][v] = val;
            }
            if (t < TJ)            ssj[t] = g_sames[i * N + j0 + t];
            else if (t < TJ + TK)  ssk[t - TJ] = g_sames[i * N + k0 + (t - TJ)];
        }
        __syncthreads();

        const bool diag = (jt == kt);
        const uint4 z = make_uint4(0u, 0u, 0u, 0u);

        #pragma unroll
        for (int it = 0; it < 6; it++) {
            const int l  = it * 256 + t;             // 0..1535
            const int jj = l / (TK * 24);
            const int r  = l - jj * (TK * 24);
            const int kk = r / 24;
            const int v  = r - kk * 24;

            const bool valid = ssj[jj] && ssk[kk] && (!diag || jj < kk);
            uint4 res = z;
            if (valid) {
                const uint4 a = sBj[jj][v];
                const uint4 b = sBk[kk][v];
                res = make_uint4(a.x | b.x, a.y | b.y, a.z | b.z, a.w | b.w);
            }
            obase[(size_t)jj * (N * 24) + r] = res;
        }
    }
}

// ---------------------------------------------------------------------------
extern "C" void kernel_launch(void* const* d_in, const int* in_sizes, int n_in,
                              void* d_out, int out_size) {
    const float* logits = (const float*)d_in[0];   // [96, 64]
    const float* labels = (const float*)d_in[1];   // [96, 21]
    const float* feat2  = (const float*)d_in[2];   // [96, 64]

    // reset prep counter (D2D copy of a device-resident zero word; capturable)
    void* flag_addr = nullptr;
    void* zero_addr = nullptr;
    cudaGetSymbolAddress(&flag_addr, g_flag);
    cudaGetSymbolAddress(&zero_addr, g_zero);
    cudaMemcpyAsync(flag_addr, zero_addr, sizeof(int),
                    cudaMemcpyDeviceToDevice);

    miner_kernel<<<NBLK_TOTAL, 256>>>(logits, labels, feat2, (uint4*)d_out);
}

// round 17
// speedup vs baseline: 1.2280x; 1.2280x over previous
#include <cuda_runtime.h>
#include <stdint.h>

#define N 96
#define D 64
#define C 21
#define MARGIN_F 0.3f
#define ONE_F_BITS 0x3F800000u

#define TJ 8
#define TK 8
#define NZPAIR 66               // #(jt,kt) with jt>kt
#define NWPAIR 78               // #(jt,kt) with jt<=kt

#define NBLK_PREP  N                      // 96
#define NBLK_ZERO  (NZPAIR * N)           // 6336
#define NBLK_WORK  (NWPAIR * N)           // 7488
#define ZERO_BASE  NBLK_PREP              // 96
#define WORK_BASE  (NBLK_PREP + NBLK_ZERO) // 6432
#define NBLK_TOTAL (WORK_BASE + NBLK_WORK) // 13920

// Scratch (no allocations allowed in kernel_launch)
__device__ unsigned char  g_sames[N * N];
// B[i,p,n] float-encoded (0x0 / 0x3F800000), 24 uint4 per (i,p). 3.4 MB, L2-resident.
__device__ uint4          g_B4[N * N * 24];
// prep-done counter; reset to 0 each call by a D2D memcpy node (g_zero -> g_flag)
__device__ int            g_flag;
__device__ const int      g_zero = 0;

// tile-pair lookup tables (literal -> zero decode cost)
__constant__ uint8_t ZJT[NZPAIR] = {
    1,
    2,2,
    3,3,3,
    4,4,4,4,
    5,5,5,5,5,
    6,6,6,6,6,6,
    7,7,7,7,7,7,7,
    8,8,8,8,8,8,8,8,
    9,9,9,9,9,9,9,9,9,
    10,10,10,10,10,10,10,10,10,10,
    11,11,11,11,11,11,11,11,11,11,11 };
__constant__ uint8_t ZKT[NZPAIR] = {
    0,
    0,1,
    0,1,2,
    0,1,2,3,
    0,1,2,3,4,
    0,1,2,3,4,5,
    0,1,2,3,4,5,6,
    0,1,2,3,4,5,6,7,
    0,1,2,3,4,5,6,7,8,
    0,1,2,3,4,5,6,7,8,9,
    0,1,2,3,4,5,6,7,8,9,10 };
__constant__ uint8_t WJT[NWPAIR] = {
    0,0,0,0,0,0,0,0,0,0,0,0,
    1,1,1,1,1,1,1,1,1,1,1,
    2,2,2,2,2,2,2,2,2,2,
    3,3,3,3,3,3,3,3,3,
    4,4,4,4,4,4,4,4,
    5,5,5,5,5,5,5,
    6,6,6,6,6,6,
    7,7,7,7,7,
    8,8,8,8,
    9,9,9,
    10,10,
    11 };
__constant__ uint8_t WKT[NWPAIR] = {
    0,1,2,3,4,5,6,7,8,9,10,11,
    1,2,3,4,5,6,7,8,9,10,11,
    2,3,4,5,6,7,8,9,10,11,
    3,4,5,6,7,8,9,10,11,
    4,5,6,7,8,9,10,11,
    5,6,7,8,9,10,11,
    6,7,8,9,10,11,
    7,8,9,10,11,
    8,9,10,11,
    9,10,11,
    10,11,
    11 };

// ---------------------------------------------------------------------------
// ONE kernel, roles by bid range.
//   prep (0..95):        compute row i of mat/sames/diffs + B slab; then
//                        __threadfence + atomicAdd(g_flag) (release-publish).
//   zero (96..6431):     unconditional zero tiles (no dependencies).
//   work (6432..13919):  t0 spins on a PLAIN volatile L2 read of g_flag
//                        (no RMW, no acquire -> no L1 side effects), then
//                        __syncthreads. Steady state: one L2 read + one BAR.
// Safety: only work blocks ever READ g_B4/g_sames, and only after the flag;
// prep's stores are L2-visible via the fence, and no SM can hold stale L1
// lines for data it never read. g_flag is reset by a D2D memcpy node.
// ---------------------------------------------------------------------------
__global__ __launch_bounds__(256, 6)
void miner_kernel(const float* __restrict__ logits,
                  const float* __restrict__ labels,
                  const float* __restrict__ feat2,
                  uint4* __restrict__ out) {
    const int bid = blockIdx.x;
    const int t   = threadIdx.x;

    // ======================= role 1: prep (bids 0..95) =====================
    if (bid < NBLK_PREP) {
        const int i = bid;
        const int j = t;

        __shared__ float         xs[D];
        __shared__ float         li[C];
        __shared__ float         inv_nx;
        __shared__ float         mrow[N];
        __shared__ unsigned char drow[N];

        if (j < D) xs[j] = logits[i * D + j];
        if (j < C) li[j] = labels[i * C + j];
        __syncthreads();

        if (j == 0) {
            float s = 0.f;
            #pragma unroll
            for (int c = 0; c < D; c++) s += xs[c] * xs[c];
            inv_nx = 1.0f / fmaxf(sqrtf(s), 1e-12f);
        }
        __syncthreads();

        if (j < N) {
            float dot = 0.f, nyy = 0.f;
            #pragma unroll
            for (int c = 0; c < D; c++) {
                float y = feat2[j * D + c];
                dot += xs[c] * y;
                nyy += y * y;
            }
            const float inv_ny = 1.0f / fmaxf(sqrtf(nyy), 1e-12f);
            mrow[j] = -(dot * inv_nx * inv_ny);

            float ld = 0.f;
            #pragma unroll
            for (int c = 0; c < C; c++) ld += li[c] * labels[j * C + c];
            const bool share = (ld > 0.0f);
            g_sames[i * N + j] = (share && (i != j)) ? 1 : 0;
            drow[j] = share ? 0 : 1;         // diagonal NOT filled (matches ref)
        }
        __syncthreads();

        if (j < N) {
            const float mp = mrow[j];
            uint4* dst = &g_B4[(i * N + j) * 24];
            #pragma unroll
            for (int v = 0; v < 24; v++) {
                uint4 w;
                w.x = (drow[4*v+0] && (mrow[4*v+0] - mp <= MARGIN_F)) ? ONE_F_BITS : 0u;
                w.y = (drow[4*v+1] && (mrow[4*v+1] - mp <= MARGIN_F)) ? ONE_F_BITS : 0u;
                w.z = (drow[4*v+2] && (mrow[4*v+2] - mp <= MARGIN_F)) ? ONE_F_BITS : 0u;
                w.w = (drow[4*v+3] && (mrow[4*v+3] - mp <= MARGIN_F)) ? ONE_F_BITS : 0u;
                dst[v] = w;
            }
        }

        // publish this i-slab
        __syncthreads();
        if (t == 0) {
            __threadfence();
            atomicAdd(&g_flag, 1);
        }
        return;
    }

    const int jj   = t >> 5;                // warp -> output j-row in tile
    const int lane = t & 31;

    // ================= role 2: zero-fill (bids 96..6431) ===================
    if (bid < WORK_BASE) {
        const int z  = bid - ZERO_BASE;
        const int i  = z / NZPAIR;
        const int p  = z - i * NZPAIR;
        const int j0 = (int)ZJT[p] * TJ;
        const int k0 = (int)ZKT[p] * TK;

        // warp jj owns out[i][j0+jj][k0..k0+8)[:] = 192 contiguous uint4
        uint4* __restrict__ orow =
            out + ((size_t)((i * N + j0 + jj) * N + k0)) * 24;
        const uint4 zv = make_uint4(0u, 0u, 0u, 0u);
        #pragma unroll
        for (int it = 0; it < 6; it++)
            orow[it * 32 + lane] = zv;
        return;
    }

    // ================= role 3: work-fill (bids 6432..13919) ================
    {
        // t0-only gate: PLAIN volatile L2 read (no RMW, no acquire scope)
        if (t == 0) {
            volatile int* vf = &g_flag;
            while (*vf < NBLK_PREP) __nanosleep(64);
        }
        __syncthreads();

        const int w  = bid - WORK_BASE;
        const int i  = w / NWPAIR;
        const int q  = w - i * NWPAIR;
        const int jt = (int)WJT[q];
        const int kt = (int)WKT[q];
        const int j0 = jt * TJ;
        const int k0 = kt * TK;

        __shared__ uint4         sBj[TJ][24];
        __shared__ uint4         sBk[TK][24];
        __shared__ unsigned char ssj[TJ];
        __shared__ unsigned char ssk[TK];

        // stage 384 uint4 (rows 0-7 -> sBj, 8-15 -> sBk)
        {
            int l = t;
            {
                const int row = l / 24, v = l % 24;
                const int src_p = (row < TJ) ? (j0 + row) : (k0 + row - TJ);
                uint4 val = g_B4[(i * N + src_p) * 24 + v];
                if (row < TJ) sBj[row][v] = val; else sBk[row - TJ][v] = val;
            }
            l = t + 256;
            if (l < 384) {
                const int row = l / 24, v = l % 24;
                const int src_p = (row < TJ) ? (j0 + row) : (k0 + row - TJ);
                uint4 val = g_B4[(i * N + src_p) * 24 + v];
                if (row < TJ) sBj[row][v] = val; else sBk[row - TJ][v] = val;
            }
            if (t < TJ)            ssj[t] = g_sames[i * N + j0 + t];
            else if (t < TJ + TK)  ssk[t - TJ] = g_sames[i * N + k0 + (t - TJ)];
        }
        __syncthreads();

        const bool diag = (jt == kt);

        // warp jj owns out row j0+jj: 192 uint4 flattened as kk*24+v
        uint4* __restrict__ orow =
            out + ((size_t)((i * N + j0 + jj) * N + k0)) * 24;
        const uint4*    aRow  = sBj[jj];
        const uint4*    bFlat = &sBk[0][0];
        const uint32_t  sjm   = ssj[jj] ? 0xFFFFFFFFu : 0u;

        // compile-time per-iteration split of it*32 = 24*Q + R:
        //   kk = Q + carry,  v = lane + R - 24*carry,  carry = (lane+R >= 24)
        #pragma unroll
        for (int it = 0; it < 6; it++) {
            const int base = it * 32;                 // literal
            const int Q    = base / 24;               // literal
            const int R    = base - Q * 24;           // literal
            const int lr   = lane + R;
            const int c    = (lr >= 24) ? 1 : 0;
            const int kk   = Q + c;
            const int v    = lr - 24 * c;
            const int idx  = base + lane;

            const bool ok  = ssk[kk] && (!diag || jj < kk);
            const uint32_t mask = ok ? sjm : 0u;

            const uint4 a = aRow[v];
            const uint4 b = bFlat[idx];
            uint4 res;
            res.x = (a.x | b.x) & mask;
            res.y = (a.y | b.y) & mask;
            res.z = (a.z | b.z) & mask;
            res.w = (a.w | b.w) & mask;
            orow[idx] = res;
        }
    }
}

// ---------------------------------------------------------------------------
extern "C" void kernel_launch(void* const* d_in, const int* in_sizes, int n_in,
                              void* d_out, int out_size) {
    const float* logits = (const float*)d_in[0];   // [96, 64]
    const float* labels = (const float*)d_in[1];   // [96, 21]
    const float* feat2  = (const float*)d_in[2];   // [96, 64]

    // reset prep counter (D2D copy of a device-resident zero word; capturable)
    void* flag_addr = nullptr;
    void* zero_addr = nullptr;
    cudaGetSymbolAddress(&flag_addr, g_flag);
    cudaGetSymbolAddress(&zero_addr, g_zero);
    cudaMemcpyAsync(flag_addr, zero_addr, sizeof(int),
                    cudaMemcpyDeviceToDevice);

    miner_kernel<<<NBLK_TOTAL, 256>>>(logits, labels, feat2, (uint4*)d_out);
}